// round 8
// baseline (speedup 1.0000x reference)
#include <cuda_runtime.h>
#include <cuda_bf16.h>
#include <math.h>

// ---------------------------------------------------------------------------
// Problem constants
// ---------------------------------------------------------------------------
#define NUM_CLS 80
#define NROIS   256
#define KFEAT   12544   // 256 * 49
#define H1DIM   1024
#define LOC_OFF 82944   // 4*256*81 floats into g_part (loc partials start)

// scratch (device globals; no allocation)
__device__ float g_T0[65536 * 256];   // P0 transposed HWC
__device__ float g_T1[16384 * 256];
__device__ float g_T2[4096 * 256];
__device__ float g_T3[1024 * 256];
__device__ float g_pool[NROIS * KFEAT];        // [n][bin*256 + c]
__device__ float g_part[8 * NROIS * 1024];     // split-K partials (reused)
__device__ float g_h1[NROIS * H1DIM];
__device__ float g_h2[NROIS * H1DIM];
__device__ float g_roi[NROIS * 4];
__device__ float g_valid[NROIS];
__device__ float g_preb[NROIS * NUM_CLS * 4];
__device__ float g_pres[NROIS * NUM_CLS];

__constant__ float4 c_stds[3] = {
    {0.1f, 0.1f, 0.2f, 0.2f},
    {0.05f, 0.05f, 0.1f, 0.1f},
    {1.0f / 30.0f, 1.0f / 30.0f, 1.0f / 15.0f, 1.0f / 15.0f}
};

// ---------------------------------------------------------------------------
// f32x2 packed FMA helpers (sm_103a)
// ---------------------------------------------------------------------------
__device__ __forceinline__ unsigned long long dup_f(float x) {
    unsigned long long r;
    asm("mov.b64 %0, {%1, %1};" : "=l"(r) : "f"(x));
    return r;
}
__device__ __forceinline__ void fma2(unsigned long long& d, unsigned long long a,
                                     unsigned long long b) {
    asm("fma.rn.f32x2 %0, %1, %2, %0;" : "+l"(d) : "l"(a), "l"(b));
}
__device__ __forceinline__ float2 unpack2(unsigned long long v) {
    float2 r;
    asm("mov.b64 {%0, %1}, %2;" : "=f"(r.x), "=f"(r.y) : "l"(v));
    return r;
}

// ---------------------------------------------------------------------------
// Fused transpose: all 4 levels [C][HW] -> [HW][C]
// grid = (2720, 8), block = (32, 8)
// ---------------------------------------------------------------------------
__global__ void transpose_all(const float* __restrict__ P0,
                              const float* __restrict__ P1,
                              const float* __restrict__ P2,
                              const float* __restrict__ P3) {
    __shared__ float tile[32][33];
    int bx = blockIdx.x;
    int p, HW;
    const float* src;
    float* dst;
    if (bx < 2048)      { p = bx;        HW = 65536; src = P0; dst = g_T0; }
    else if (bx < 2560) { p = bx - 2048; HW = 16384; src = P1; dst = g_T1; }
    else if (bx < 2688) { p = bx - 2560; HW = 4096;  src = P2; dst = g_T2; }
    else                { p = bx - 2688; HW = 1024;  src = P3; dst = g_T3; }

    int pBase = p * 32;
    int cBase = blockIdx.y * 32;
    int tx = threadIdx.x, ty = threadIdx.y;
#pragma unroll
    for (int r = 0; r < 4; r++)
        tile[ty + 8 * r][tx] = src[(size_t)(cBase + ty + 8 * r) * HW + pBase + tx];
    __syncthreads();
#pragma unroll
    for (int r = 0; r < 4; r++)
        dst[(size_t)(pBase + ty + 8 * r) * 256 + cBase + tx] = tile[tx][ty + 8 * r];
}

// ---------------------------------------------------------------------------
// Init accumulators / roi state
// ---------------------------------------------------------------------------
__global__ void init_state(const float* __restrict__ rois) {
    int idx = blockIdx.x * 256 + threadIdx.x;   // grid covers 81920
    if (idx < NROIS * NUM_CLS * 4) g_preb[idx] = 0.0f;
    if (idx < NROIS * NUM_CLS)     g_pres[idx] = 0.0f;
    if (idx < NROIS * 4)           g_roi[idx] = rois[idx];
    if (idx < NROIS)               g_valid[idx] = 1.0f;
}

// ---------------------------------------------------------------------------
// ROIAlign (out=7, SR=2) on channels-last features.
// ---------------------------------------------------------------------------
__global__ void roialign_kernel() {
    const int n = blockIdx.x;
    const int tid = threadIdx.x;

    __shared__ int   s_iy0[14], s_iy1[14], s_ix0[14], s_ix1[14];
    __shared__ float s_ly[14], s_lx[14];
    __shared__ int   s_vy[14], s_vx[14];
    __shared__ int   s_lvl;

    const float r0 = g_roi[n * 4 + 0];
    const float r1 = g_roi[n * 4 + 1];
    const float r2 = g_roi[n * 4 + 2];
    const float r3 = g_roi[n * 4 + 3];

    if (tid == 0) {
        float area = (r2 - r0 + 1.0f) * (r3 - r1 + 1.0f);
        float lv = floorf(4.0f + log2f(sqrtf(area) / 224.0f));
        lv = fminf(fmaxf(lv, 2.0f), 5.0f) - 2.0f;
        s_lvl = (int)lv;
    }
    __syncthreads();

    const int l = s_lvl;
    const int Hdims[4] = {256, 128, 64, 32};
    const float scales[4] = {0.25f, 0.125f, 0.0625f, 0.03125f};
    const int H = Hdims[l];
    const int W = H;
    const float scale = scales[l];

    if (tid < 28) {
        bool isx = tid >= 14;
        int t = isx ? tid - 14 : tid;
        float a  = isx ? r1 : r0;
        float b2 = isx ? r3 : r2;
        float lo = a * scale;
        float len = fmaxf(b2 * scale - lo, 1.0f);
        float g = (float)(t >> 1) + ((float)(t & 1) + 0.5f) * 0.5f;
        float coord = lo + g * (len / 7.0f);
        int v = (coord > -1.0f) && (coord < (float)H);
        float cc = fminf(fmaxf(coord, 0.0f), (float)H - 1.0f);
        float f0 = floorf(cc);
        int i0 = (int)f0;
        int i1 = min(i0 + 1, H - 1);
        float fr = cc - f0;
        if (isx) { s_vx[t] = v; s_ix0[t] = i0; s_ix1[t] = i1; s_lx[t] = fr; }
        else     { s_vy[t] = v; s_iy0[t] = i0; s_iy1[t] = i1; s_ly[t] = fr; }
    }
    __syncthreads();

    const float* Ts[4] = {g_T0, g_T1, g_T2, g_T3};
    const float4* F = (const float4*)Ts[l];

    const int c4 = tid & 63;    // channel group (4 channels)
    const int grp = tid >> 6;   // 4 bin groups
    float4* outp = (float4*)(g_pool + (size_t)n * KFEAT);

    for (int bin = grp; bin < 49; bin += 4) {
        int oy = bin / 7;
        int ox = bin - oy * 7;
        float4 acc = {0.f, 0.f, 0.f, 0.f};
#pragma unroll
        for (int jy = 0; jy < 2; jy++) {
            int sy = oy * 2 + jy;
            int vy = s_vy[sy];
            float ly = s_ly[sy];
            int y0 = s_iy0[sy], y1i = s_iy1[sy];
#pragma unroll
            for (int jx = 0; jx < 2; jx++) {
                int sx = ox * 2 + jx;
                if (vy && s_vx[sx]) {
                    float lx = s_lx[sx];
                    int x0 = s_ix0[sx], x1i = s_ix1[sx];
                    float4 f00 = F[(size_t)(y0 * W + x0) * 64 + c4];
                    float4 f01 = F[(size_t)(y0 * W + x1i) * 64 + c4];
                    float4 f10 = F[(size_t)(y1i * W + x0) * 64 + c4];
                    float4 f11 = F[(size_t)(y1i * W + x1i) * 64 + c4];
                    float w00 = (1.f - ly) * (1.f - lx);
                    float w01 = (1.f - ly) * lx;
                    float w10 = ly * (1.f - lx);
                    float w11 = ly * lx;
                    acc.x += f00.x * w00 + f01.x * w01 + f10.x * w10 + f11.x * w11;
                    acc.y += f00.y * w00 + f01.y * w01 + f10.y * w10 + f11.y * w11;
                    acc.z += f00.z * w00 + f01.z * w01 + f10.z * w10 + f11.z * w11;
                    acc.w += f00.w * w00 + f01.w * w01 + f10.w * w10 + f11.w * w11;
                }
            }
        }
        acc.x *= 0.25f; acc.y *= 0.25f; acc.z *= 0.25f; acc.w *= 0.25f;
        outp[bin * 64 + c4] = acc;
    }
}

// ---------------------------------------------------------------------------
// Split-K GEMM core, fp32 with packed f32x2 FMA, 2-stage smem double buffer.
// C[M=256, N] = A[256, Ktot] * B[Ktot, N] into per-split partials P.
// PERM: B row index remap k -> (k%256)*49 + (k/256) (pool layout -> W1 rows).
// ---------------------------------------------------------------------------
#define BM 64
#define BN 64
#define TK 16

template <bool PERM>
__device__ __forceinline__ void gemm_core(
    const float* __restrict__ A, const float* __restrict__ B,
    int N, int Ktot, int Kc, int split, int mBase, int nBase,
    float* __restrict__ P) {

    __shared__ float As[2][TK][BM + 4];
    __shared__ float Bs[2][TK][BN + 4];

    const int tid = threadIdx.x;
    const int k0 = split * Kc;

    const int am = tid >> 2;          // A row within tile
    const int ak = (tid & 3) * 4;     // A k-offset
    const int bk = tid >> 4;          // B row within k-tile
    const int bj = (tid & 15) * 4;    // B col offset
    const int tx = tid & 15;
    const int ty = tid >> 4;

    unsigned long long acc[2][4];
#pragma unroll
    for (int p = 0; p < 2; p++)
#pragma unroll
        for (int q = 0; q < 4; q++) acc[p][q] = 0ull;

    const bool nfull = ((nBase + BN) <= N) && ((N & 3) == 0);
    const float* Arow = A + (size_t)(mBase + am) * Ktot + k0 + ak;
    const int ntiles = Kc / TK;

    // ---- prologue: tile 0 -> smem[0]
    {
        float4 av = *(const float4*)(Arow);
        int kk = k0 + bk;
        int krow = PERM ? ((kk & 255) * 49 + (kk >> 8)) : kk;
        const float* Bp = B + (size_t)krow * N + nBase + bj;
        float4 bv;
        if (nfull) bv = *(const float4*)Bp;
        else {
            bv.x = (nBase + bj + 0 < N) ? Bp[0] : 0.0f;
            bv.y = (nBase + bj + 1 < N) ? Bp[1] : 0.0f;
            bv.z = (nBase + bj + 2 < N) ? Bp[2] : 0.0f;
            bv.w = (nBase + bj + 3 < N) ? Bp[3] : 0.0f;
        }
        As[0][ak + 0][am] = av.x;
        As[0][ak + 1][am] = av.y;
        As[0][ak + 2][am] = av.z;
        As[0][ak + 3][am] = av.w;
        *(float4*)&Bs[0][bk][bj] = bv;
    }
    __syncthreads();

    int buf = 0;
    for (int t = 0; t < ntiles; t++) {
        // prefetch next tile into registers (LDG latency overlapped w/ compute)
        float4 avn, bvn;
        const bool more = (t + 1 < ntiles);
        if (more) {
            avn = *(const float4*)(Arow + (t + 1) * TK);
            int kk = k0 + (t + 1) * TK + bk;
            int krow = PERM ? ((kk & 255) * 49 + (kk >> 8)) : kk;
            const float* Bp = B + (size_t)krow * N + nBase + bj;
            if (nfull) bvn = *(const float4*)Bp;
            else {
                bvn.x = (nBase + bj + 0 < N) ? Bp[0] : 0.0f;
                bvn.y = (nBase + bj + 1 < N) ? Bp[1] : 0.0f;
                bvn.z = (nBase + bj + 2 < N) ? Bp[2] : 0.0f;
                bvn.w = (nBase + bj + 3 < N) ? Bp[3] : 0.0f;
            }
        }

#pragma unroll
        for (int kx = 0; kx < TK; kx++) {
            ulonglong2 ap = *(const ulonglong2*)&As[buf][kx][ty * 4];
            float4 bq = *(const float4*)&Bs[buf][kx][tx * 4];
            unsigned long long b0 = dup_f(bq.x);
            unsigned long long b1 = dup_f(bq.y);
            unsigned long long b2 = dup_f(bq.z);
            unsigned long long b3 = dup_f(bq.w);
            fma2(acc[0][0], ap.x, b0);
            fma2(acc[0][1], ap.x, b1);
            fma2(acc[0][2], ap.x, b2);
            fma2(acc[0][3], ap.x, b3);
            fma2(acc[1][0], ap.y, b0);
            fma2(acc[1][1], ap.y, b1);
            fma2(acc[1][2], ap.y, b2);
            fma2(acc[1][3], ap.y, b3);
        }

        if (more) {
            int nb = buf ^ 1;
            As[nb][ak + 0][am] = avn.x;
            As[nb][ak + 1][am] = avn.y;
            As[nb][ak + 2][am] = avn.z;
            As[nb][ak + 3][am] = avn.w;
            *(float4*)&Bs[nb][bk][bj] = bvn;
            __syncthreads();
            buf = nb;
        }
    }

#pragma unroll
    for (int p = 0; p < 2; p++) {
        int m = mBase + ty * 4 + p * 2;
#pragma unroll
        for (int q = 0; q < 4; q++) {
            float2 v = unpack2(acc[p][q]);
            int col = nBase + tx * 4 + q;
            if (col < N) {
                P[(size_t)m * N + col] = v.x;
                P[(size_t)(m + 1) * N + col] = v.y;
            }
        }
    }
}

template <bool PERM>
__global__ __launch_bounds__(256) void gemm_splitk(
    const float* __restrict__ B, int Asel, int N, int Ktot, int Kc) {
    const float* A = (Asel == 0) ? g_pool : ((Asel == 1) ? g_h1 : g_h2);
    float* P = g_part + (size_t)blockIdx.z * NROIS * N;
    gemm_core<PERM>(A, B, N, Ktot, Kc, blockIdx.z,
                    blockIdx.y * BM, blockIdx.x * BN, P);
}

// fused cls+loc head GEMM: grid.x in [0,8): 0-1 -> Wc (N=81), 2-7 -> Wl (N=324)
__global__ __launch_bounds__(256) void gemm_heads(
    const float* __restrict__ Wc, const float* __restrict__ Wl) {
    int bx = blockIdx.x;
    const float* Bsel;
    int N, nBase;
    float* P;
    if (bx < 2) {
        Bsel = Wc; N = 81; nBase = bx * BN;
        P = g_part + (size_t)blockIdx.z * NROIS * 81;
    } else {
        Bsel = Wl; N = 324; nBase = (bx - 2) * BN;
        P = g_part + LOC_OFF + (size_t)blockIdx.z * NROIS * 324;
    }
    gemm_core<false>(g_h2, Bsel, N, 1024, 256, blockIdx.z,
                     blockIdx.y * BM, nBase, P);
}

// fixed-order split reduction + bias + relu (FC1/FC2 outputs)
__global__ void reduce_bias(const float* __restrict__ bias, int outSel,
                            int splits) {
    float* out = outSel ? g_h2 : g_h1;
    int idx = blockIdx.x * 256 + threadIdx.x;   // grid covers 256*1024
    const int MN = NROIS * 1024;
    float s = 0.0f;
    for (int sp = 0; sp < splits; sp++) s += g_part[(size_t)sp * MN + idx];
    s += bias[idx & 1023];
    out[idx] = fmaxf(s, 0.0f);
}

// ---------------------------------------------------------------------------
// Fused head epilogue: reduce cls/loc partials + bias, softmax, box decode,
// accumulate, argmax, roi update, valid mask. One block per roi, 128 threads.
// ---------------------------------------------------------------------------
__global__ void head_post(const float* __restrict__ bc,
                          const float* __restrict__ bl, int stage) {
    const int n = blockIdx.x;
    const int tid = threadIdx.x;

    __shared__ float sl[81];
    __shared__ float sloc[324];
    __shared__ float ssc[80];
    __shared__ float sbox[80][4];
    __shared__ float sred[128];
    __shared__ int sidx[128];

    if (tid < 81) {
        float s = 0.0f;
#pragma unroll
        for (int sp = 0; sp < 4; sp++)
            s += g_part[(size_t)sp * (NROIS * 81) + n * 81 + tid];
        sl[tid] = s + bc[tid];
    }
    for (int i = tid; i < 324; i += 128) {
        float s = 0.0f;
#pragma unroll
        for (int sp = 0; sp < 4; sp++)
            s += g_part[LOC_OFF + (size_t)sp * (NROIS * 324) + n * 324 + i];
        sloc[i] = s + bl[i];
    }
    __syncthreads();

    // softmax max
    float m = (tid < 81) ? sl[tid] : -1e30f;
    sred[tid] = m;
    __syncthreads();
    for (int off = 64; off > 0; off >>= 1) {
        if (tid < off) sred[tid] = fmaxf(sred[tid], sred[tid + off]);
        __syncthreads();
    }
    const float M = sred[0];
    __syncthreads();

    // exp-sum
    float e = (tid < 81) ? expf(sl[tid] - M) : 0.0f;
    sred[tid] = e;
    __syncthreads();
    for (int off = 64; off > 0; off >>= 1) {
        if (tid < off) sred[tid] += sred[tid + off];
        __syncthreads();
    }
    const float S = sred[0];
    __syncthreads();
    if (tid >= 1 && tid < 81) ssc[tid - 1] = e / S;
    __syncthreads();

    const float r0 = g_roi[n * 4 + 0];
    const float r1 = g_roi[n * 4 + 1];
    const float r2 = g_roi[n * 4 + 2];
    const float r3 = g_roi[n * 4 + 3];
    const float chy = r2 - r0, chx = r3 - r1;
    const float cy = r0 + chy * 0.5f, cx = r1 + chx * 0.5f;
    const float4 stds = c_stds[stage];

    if (tid < 80) {
        const int j = tid;
        g_pres[n * 80 + j] += ssc[j];
        const float* lp = sloc + (j + 1) * 4;
        float l0 = lp[0] * stds.x;
        float l1 = lp[1] * stds.y;
        float l2 = lp[2] * stds.z;
        float l3 = lp[3] * stds.w;
        float ty_ = l0 * chy + cy;
        float tx_ = l1 * chx + cx;
        float hy = expf(l2) * chy;
        float hx = expf(l3) * chx;
        float b0 = ty_ - hy * 0.5f;
        float b1 = tx_ - hx * 0.5f;
        float b2 = ty_ + hy * 0.5f;
        float b3 = tx_ + hx * 0.5f;
        sbox[j][0] = b0; sbox[j][1] = b1; sbox[j][2] = b2; sbox[j][3] = b3;
        float* pb = g_preb + (size_t)(n * 80 + j) * 4;
        pb[0] += b0; pb[1] += b1; pb[2] += b2; pb[3] += b3;
    }

    // argmax (first occurrence on ties)
    sred[tid] = (tid < 80) ? ssc[tid] : -1e30f;
    sidx[tid] = (tid < 80) ? tid : (1 << 30);
    __syncthreads();
    for (int off = 64; off > 0; off >>= 1) {
        if (tid < off) {
            float v2 = sred[tid + off];
            int i2 = sidx[tid + off];
            if (v2 > sred[tid] || (v2 == sred[tid] && i2 < sidx[tid])) {
                sred[tid] = v2;
                sidx[tid] = i2;
            }
        }
        __syncthreads();
    }
    if (tid == 0) {
        int best = sidx[0];
        float nr0 = fminf(fmaxf(sbox[best][0], 0.0f), 1024.0f);
        float nr1 = fminf(fmaxf(sbox[best][1], 0.0f), 1024.0f);
        float nr2 = fminf(fmaxf(sbox[best][2], 0.0f), 1024.0f);
        float nr3 = fminf(fmaxf(sbox[best][3], 0.0f), 1024.0f);
        g_roi[n * 4 + 0] = nr0;
        g_roi[n * 4 + 1] = nr1;
        g_roi[n * 4 + 2] = nr2;
        g_roi[n * 4 + 3] = nr3;
        if (stage < 2) {
            float hy = nr2 - nr0, hx = nr3 - nr1;
            if (!(hy >= 16.0f && hx >= 16.0f)) g_valid[n] = 0.0f;
        }
    }
}

// final: d_out = [pre_b/3*m (81920) | pre_s/3*m (20480)]
__global__ void finalize_kernel(float* __restrict__ out) {
    int idx = blockIdx.x * 256 + threadIdx.x;   // grid covers 81920
    if (idx < NROIS * NUM_CLS * 4) {
        int n = idx / (NUM_CLS * 4);
        out[idx] = g_preb[idx] * (1.0f / 3.0f) * g_valid[n];
    }
    if (idx < NROIS * NUM_CLS) {
        int n = idx / NUM_CLS;
        out[NROIS * NUM_CLS * 4 + idx] = g_pres[idx] * (1.0f / 3.0f) * g_valid[n];
    }
}

// ---------------------------------------------------------------------------
// launch
// ---------------------------------------------------------------------------
extern "C" void kernel_launch(void* const* d_in, const int* in_sizes, int n_in,
                              void* d_out, int out_size) {
    (void)in_sizes; (void)n_in; (void)out_size;
    const float* P0 = (const float*)d_in[0];
    const float* P1 = (const float*)d_in[1];
    const float* P2 = (const float*)d_in[2];
    const float* P3 = (const float*)d_in[3];
    const float* rois = (const float*)d_in[4];

    transpose_all<<<dim3(2720, 8), dim3(32, 8)>>>(P0, P1, P2, P3);
    init_state<<<320, 256>>>(rois);

    for (int s = 0; s < 3; s++) {
        const float* W1 = (const float*)d_in[5 + 8 * s + 0];
        const float* b1 = (const float*)d_in[5 + 8 * s + 1];
        const float* W2 = (const float*)d_in[5 + 8 * s + 2];
        const float* b2 = (const float*)d_in[5 + 8 * s + 3];
        const float* Wc = (const float*)d_in[5 + 8 * s + 4];
        const float* bc = (const float*)d_in[5 + 8 * s + 5];
        const float* Wl = (const float*)d_in[5 + 8 * s + 6];
        const float* bl = (const float*)d_in[5 + 8 * s + 7];

        roialign_kernel<<<NROIS, 256>>>();

        // FC1: [256,12544] x [12544,1024], split-K=8
        gemm_splitk<true><<<dim3(16, 4, 8), 256>>>(W1, 0, 1024, 12544, 1568);
        reduce_bias<<<1024, 256>>>(b1, 0, 8);

        // FC2: [256,1024] x [1024,1024], split-K=4
        gemm_splitk<false><<<dim3(16, 4, 4), 256>>>(W2, 1, 1024, 1024, 256);
        reduce_bias<<<1024, 256>>>(b2, 1, 4);

        // heads (cls + loc fused), split-K=4
        gemm_heads<<<dim3(8, 4, 4), 256>>>(Wc, Wl);
        head_post<<<NROIS, 128>>>(bc, bl, s);
    }

    finalize_kernel<<<320, 256>>>((float*)d_out);
}

// round 9
// speedup vs baseline: 1.1231x; 1.1231x over previous
#include <cuda_runtime.h>
#include <cuda_bf16.h>
#include <math.h>

// ---------------------------------------------------------------------------
// Problem constants
// ---------------------------------------------------------------------------
#define NUM_CLS 80
#define NROIS   256
#define KFEAT   12544   // 256 * 49
#define H1DIM   1024
#define LOC_OFF 82944   // 4*256*81 floats into g_part (loc partials start)

// scratch (device globals; no allocation)
__device__ float g_T0[65536 * 256];   // P0 transposed HWC
__device__ float g_T1[16384 * 256];
__device__ float g_T2[4096 * 256];
__device__ float g_T3[1024 * 256];
__device__ float g_pool[NROIS * KFEAT];        // [n][bin*256 + c]
__device__ float g_part[8 * NROIS * 1024];     // split-K partials (reused)
__device__ float g_h1[NROIS * H1DIM];
__device__ float g_h2[NROIS * H1DIM];
__device__ float g_roi[NROIS * 4];
__device__ float g_valid[NROIS];
__device__ float g_preb[NROIS * NUM_CLS * 4];
__device__ float g_pres[NROIS * NUM_CLS];

__constant__ float4 c_stds[3] = {
    {0.1f, 0.1f, 0.2f, 0.2f},
    {0.05f, 0.05f, 0.1f, 0.1f},
    {1.0f / 30.0f, 1.0f / 30.0f, 1.0f / 15.0f, 1.0f / 15.0f}
};

// ---------------------------------------------------------------------------
// f32x2 packed FMA helpers (sm_103a)
// ---------------------------------------------------------------------------
__device__ __forceinline__ unsigned long long dup_f(float x) {
    unsigned long long r;
    asm("mov.b64 %0, {%1, %1};" : "=l"(r) : "f"(x));
    return r;
}
__device__ __forceinline__ void fma2(unsigned long long& d, unsigned long long a,
                                     unsigned long long b) {
    asm("fma.rn.f32x2 %0, %1, %2, %0;" : "+l"(d) : "l"(a), "l"(b));
}
__device__ __forceinline__ float2 unpack2(unsigned long long v) {
    float2 r;
    asm("mov.b64 {%0, %1}, %2;" : "=f"(r.x), "=f"(r.y) : "l"(v));
    return r;
}

// ---------------------------------------------------------------------------
// Fused transpose: all 4 levels [C][HW] -> [HW][C]
// grid = (2720, 8), block = (32, 8)
// ---------------------------------------------------------------------------
__global__ void transpose_all(const float* __restrict__ P0,
                              const float* __restrict__ P1,
                              const float* __restrict__ P2,
                              const float* __restrict__ P3) {
    __shared__ float tile[32][33];
    int bx = blockIdx.x;
    int p, HW;
    const float* src;
    float* dst;
    if (bx < 2048)      { p = bx;        HW = 65536; src = P0; dst = g_T0; }
    else if (bx < 2560) { p = bx - 2048; HW = 16384; src = P1; dst = g_T1; }
    else if (bx < 2688) { p = bx - 2560; HW = 4096;  src = P2; dst = g_T2; }
    else                { p = bx - 2688; HW = 1024;  src = P3; dst = g_T3; }

    int pBase = p * 32;
    int cBase = blockIdx.y * 32;
    int tx = threadIdx.x, ty = threadIdx.y;
#pragma unroll
    for (int r = 0; r < 4; r++)
        tile[ty + 8 * r][tx] = src[(size_t)(cBase + ty + 8 * r) * HW + pBase + tx];
    __syncthreads();
#pragma unroll
    for (int r = 0; r < 4; r++)
        dst[(size_t)(pBase + ty + 8 * r) * 256 + cBase + tx] = tile[tx][ty + 8 * r];
}

// ---------------------------------------------------------------------------
// Init accumulators / roi state
// ---------------------------------------------------------------------------
__global__ void init_state(const float* __restrict__ rois) {
    int idx = blockIdx.x * 256 + threadIdx.x;   // grid covers 81920
    if (idx < NROIS * NUM_CLS * 4) g_preb[idx] = 0.0f;
    if (idx < NROIS * NUM_CLS)     g_pres[idx] = 0.0f;
    if (idx < NROIS * 4)           g_roi[idx] = rois[idx];
    if (idx < NROIS)               g_valid[idx] = 1.0f;
}

// ---------------------------------------------------------------------------
// ROIAlign (out=7, SR=2) on channels-last features.
// ---------------------------------------------------------------------------
__global__ void roialign_kernel() {
    const int n = blockIdx.x;
    const int tid = threadIdx.x;

    __shared__ int   s_iy0[14], s_iy1[14], s_ix0[14], s_ix1[14];
    __shared__ float s_ly[14], s_lx[14];
    __shared__ int   s_vy[14], s_vx[14];
    __shared__ int   s_lvl;

    const float r0 = g_roi[n * 4 + 0];
    const float r1 = g_roi[n * 4 + 1];
    const float r2 = g_roi[n * 4 + 2];
    const float r3 = g_roi[n * 4 + 3];

    if (tid == 0) {
        float area = (r2 - r0 + 1.0f) * (r3 - r1 + 1.0f);
        float lv = floorf(4.0f + log2f(sqrtf(area) / 224.0f));
        lv = fminf(fmaxf(lv, 2.0f), 5.0f) - 2.0f;
        s_lvl = (int)lv;
    }
    __syncthreads();

    const int l = s_lvl;
    const int Hdims[4] = {256, 128, 64, 32};
    const float scales[4] = {0.25f, 0.125f, 0.0625f, 0.03125f};
    const int H = Hdims[l];
    const int W = H;
    const float scale = scales[l];

    if (tid < 28) {
        bool isx = tid >= 14;
        int t = isx ? tid - 14 : tid;
        float a  = isx ? r1 : r0;
        float b2 = isx ? r3 : r2;
        float lo = a * scale;
        float len = fmaxf(b2 * scale - lo, 1.0f);
        float g = (float)(t >> 1) + ((float)(t & 1) + 0.5f) * 0.5f;
        float coord = lo + g * (len / 7.0f);
        int v = (coord > -1.0f) && (coord < (float)H);
        float cc = fminf(fmaxf(coord, 0.0f), (float)H - 1.0f);
        float f0 = floorf(cc);
        int i0 = (int)f0;
        int i1 = min(i0 + 1, H - 1);
        float fr = cc - f0;
        if (isx) { s_vx[t] = v; s_ix0[t] = i0; s_ix1[t] = i1; s_lx[t] = fr; }
        else     { s_vy[t] = v; s_iy0[t] = i0; s_iy1[t] = i1; s_ly[t] = fr; }
    }
    __syncthreads();

    const float* Ts[4] = {g_T0, g_T1, g_T2, g_T3};
    const float4* F = (const float4*)Ts[l];

    const int c4 = tid & 63;    // channel group (4 channels)
    const int grp = tid >> 6;   // 4 bin groups
    float4* outp = (float4*)(g_pool + (size_t)n * KFEAT);

    for (int bin = grp; bin < 49; bin += 4) {
        int oy = bin / 7;
        int ox = bin - oy * 7;
        float4 acc = {0.f, 0.f, 0.f, 0.f};
#pragma unroll
        for (int jy = 0; jy < 2; jy++) {
            int sy = oy * 2 + jy;
            int vy = s_vy[sy];
            float ly = s_ly[sy];
            int y0 = s_iy0[sy], y1i = s_iy1[sy];
#pragma unroll
            for (int jx = 0; jx < 2; jx++) {
                int sx = ox * 2 + jx;
                if (vy && s_vx[sx]) {
                    float lx = s_lx[sx];
                    int x0 = s_ix0[sx], x1i = s_ix1[sx];
                    float4 f00 = F[(size_t)(y0 * W + x0) * 64 + c4];
                    float4 f01 = F[(size_t)(y0 * W + x1i) * 64 + c4];
                    float4 f10 = F[(size_t)(y1i * W + x0) * 64 + c4];
                    float4 f11 = F[(size_t)(y1i * W + x1i) * 64 + c4];
                    float w00 = (1.f - ly) * (1.f - lx);
                    float w01 = (1.f - ly) * lx;
                    float w10 = ly * (1.f - lx);
                    float w11 = ly * lx;
                    acc.x += f00.x * w00 + f01.x * w01 + f10.x * w10 + f11.x * w11;
                    acc.y += f00.y * w00 + f01.y * w01 + f10.y * w10 + f11.y * w11;
                    acc.z += f00.z * w00 + f01.z * w01 + f10.z * w10 + f11.z * w11;
                    acc.w += f00.w * w00 + f01.w * w01 + f10.w * w10 + f11.w * w11;
                }
            }
        }
        acc.x *= 0.25f; acc.y *= 0.25f; acc.z *= 0.25f; acc.w *= 0.25f;
        outp[bin * 64 + c4] = acc;
    }
}

// ---------------------------------------------------------------------------
// 128x128 split-K GEMM, fp32 f32x2, 8x8 per-thread register tile.
// C[M=256, N(mult of 128)] = A[256, Ktot] * B[Ktot, N] -> per-split partials.
// PERM: B row remap k -> (k%256)*49 + (k/256) (pool layout -> W1 rows).
// grid = (N/128, M/128, splits), 256 threads. Kc must be a multiple of 16.
// ---------------------------------------------------------------------------
template <bool PERM>
__global__ __launch_bounds__(256) void gemm128(
    const float* __restrict__ B, int Asel, int N, int Ktot, int Kc) {
    const float* A = (Asel == 0) ? g_pool : ((Asel == 1) ? g_h1 : g_h2);

    __shared__ float As[2][16][132];
    __shared__ float Bs[2][16][136];

    const int tid = threadIdx.x;
    const int k0 = blockIdx.z * Kc;
    const int mBase = blockIdx.y * 128;
    const int nBase = blockIdx.x * 128;

    // A-load mapping: thread loads rows lm and lm+64, k-slice lk..lk+3
    const int lm = tid >> 2;          // 0..63
    const int lk = (tid & 3) * 4;     // 0,4,8,12
    // B-load mapping: row bk, cols bj..bj+7
    const int bk = tid >> 4;          // 0..15
    const int bj = (tid & 15) * 8;    // 0..120

    // compute mapping: 8 warps as 4(M) x 2(N); lane as 4(r) x 8(c)
    const int wid = tid >> 5, lane = tid & 31;
    const int tm = (wid >> 1) * 32 + (lane >> 3) * 8;   // 8 rows tm..tm+7
    const int tn = (wid & 1) * 64 + (lane & 7) * 8;     // 8 cols tn..tn+7

    unsigned long long acc[4][8];
#pragma unroll
    for (int p = 0; p < 4; p++)
#pragma unroll
        for (int q = 0; q < 8; q++) acc[p][q] = 0ull;

    const float* Arow0 = A + (size_t)(mBase + lm) * Ktot + k0 + lk;
    const float* Arow1 = Arow0 + (size_t)64 * Ktot;
    const int ntiles = Kc / 16;

    // ---- prologue: tile 0 -> smem[0]
    {
        float4 a0 = *(const float4*)(Arow0);
        float4 a1 = *(const float4*)(Arow1);
        int kk = k0 + bk;
        int krow = PERM ? ((kk & 255) * 49 + (kk >> 8)) : kk;
        const float* Bp = B + (size_t)krow * N + nBase + bj;
        float4 b0 = *(const float4*)(Bp);
        float4 b1 = *(const float4*)(Bp + 4);
        As[0][lk + 0][lm] = a0.x;  As[0][lk + 1][lm] = a0.y;
        As[0][lk + 2][lm] = a0.z;  As[0][lk + 3][lm] = a0.w;
        As[0][lk + 0][lm + 64] = a1.x;  As[0][lk + 1][lm + 64] = a1.y;
        As[0][lk + 2][lm + 64] = a1.z;  As[0][lk + 3][lm + 64] = a1.w;
        *(float4*)&Bs[0][bk][bj] = b0;
        *(float4*)&Bs[0][bk][bj + 4] = b1;
    }
    __syncthreads();

    int buf = 0;
    for (int t = 0; t < ntiles; t++) {
        float4 a0n, a1n, b0n, b1n;
        const bool more = (t + 1 < ntiles);
        if (more) {
            a0n = *(const float4*)(Arow0 + (t + 1) * 16);
            a1n = *(const float4*)(Arow1 + (t + 1) * 16);
            int kk = k0 + (t + 1) * 16 + bk;
            int krow = PERM ? ((kk & 255) * 49 + (kk >> 8)) : kk;
            const float* Bp = B + (size_t)krow * N + nBase + bj;
            b0n = *(const float4*)(Bp);
            b1n = *(const float4*)(Bp + 4);
        }

#pragma unroll
        for (int kx = 0; kx < 16; kx++) {
            ulonglong2 ua0 = *(const ulonglong2*)&As[buf][kx][tm];
            ulonglong2 ua1 = *(const ulonglong2*)&As[buf][kx][tm + 4];
            float4 bf0 = *(const float4*)&Bs[buf][kx][tn];
            float4 bf1 = *(const float4*)&Bs[buf][kx][tn + 4];
            unsigned long long bd[8];
            bd[0] = dup_f(bf0.x); bd[1] = dup_f(bf0.y);
            bd[2] = dup_f(bf0.z); bd[3] = dup_f(bf0.w);
            bd[4] = dup_f(bf1.x); bd[5] = dup_f(bf1.y);
            bd[6] = dup_f(bf1.z); bd[7] = dup_f(bf1.w);
#pragma unroll
            for (int q = 0; q < 8; q++) {
                fma2(acc[0][q], ua0.x, bd[q]);
                fma2(acc[1][q], ua0.y, bd[q]);
                fma2(acc[2][q], ua1.x, bd[q]);
                fma2(acc[3][q], ua1.y, bd[q]);
            }
        }

        if (more) {
            int nb = buf ^ 1;
            As[nb][lk + 0][lm] = a0n.x;  As[nb][lk + 1][lm] = a0n.y;
            As[nb][lk + 2][lm] = a0n.z;  As[nb][lk + 3][lm] = a0n.w;
            As[nb][lk + 0][lm + 64] = a1n.x;  As[nb][lk + 1][lm + 64] = a1n.y;
            As[nb][lk + 2][lm + 64] = a1n.z;  As[nb][lk + 3][lm + 64] = a1n.w;
            *(float4*)&Bs[nb][bk][bj] = b0n;
            *(float4*)&Bs[nb][bk][bj + 4] = b1n;
            __syncthreads();
            buf = nb;
        }
    }

    // epilogue: 16 STG.128 (2 rows per acc pair, 8 contiguous cols each)
    float* P = g_part + (size_t)blockIdx.z * NROIS * N;
#pragma unroll
    for (int p = 0; p < 4; p++) {
        float lo[8], hi[8];
#pragma unroll
        for (int q = 0; q < 8; q++) {
            float2 v = unpack2(acc[p][q]);
            lo[q] = v.x; hi[q] = v.y;
        }
        float* r0p = P + (size_t)(mBase + tm + 2 * p) * N + nBase + tn;
        float* r1p = r0p + N;
        *(float4*)(r0p)     = make_float4(lo[0], lo[1], lo[2], lo[3]);
        *(float4*)(r0p + 4) = make_float4(lo[4], lo[5], lo[6], lo[7]);
        *(float4*)(r1p)     = make_float4(hi[0], hi[1], hi[2], hi[3]);
        *(float4*)(r1p + 4) = make_float4(hi[4], hi[5], hi[6], hi[7]);
    }
}

// ---------------------------------------------------------------------------
// 64x64 split-K GEMM core (kept for the small cls/loc head GEMMs)
// ---------------------------------------------------------------------------
#define BM 64
#define BN 64
#define TK 16

__device__ __forceinline__ void gemm_core64(
    const float* __restrict__ A, const float* __restrict__ B,
    int N, int Ktot, int Kc, int split, int mBase, int nBase,
    float* __restrict__ P) {

    __shared__ float As[2][TK][BM + 4];
    __shared__ float Bs[2][TK][BN + 4];

    const int tid = threadIdx.x;
    const int k0 = split * Kc;

    const int am = tid >> 2;
    const int ak = (tid & 3) * 4;
    const int bk = tid >> 4;
    const int bj = (tid & 15) * 4;
    const int tx = tid & 15;
    const int ty = tid >> 4;

    unsigned long long acc[2][4];
#pragma unroll
    for (int p = 0; p < 2; p++)
#pragma unroll
        for (int q = 0; q < 4; q++) acc[p][q] = 0ull;

    const bool nfull = ((nBase + BN) <= N) && ((N & 3) == 0);
    const float* Arow = A + (size_t)(mBase + am) * Ktot + k0 + ak;
    const int ntiles = Kc / TK;

    {
        float4 av = *(const float4*)(Arow);
        int kk = k0 + bk;
        const float* Bp = B + (size_t)kk * N + nBase + bj;
        float4 bv;
        if (nfull) bv = *(const float4*)Bp;
        else {
            bv.x = (nBase + bj + 0 < N) ? Bp[0] : 0.0f;
            bv.y = (nBase + bj + 1 < N) ? Bp[1] : 0.0f;
            bv.z = (nBase + bj + 2 < N) ? Bp[2] : 0.0f;
            bv.w = (nBase + bj + 3 < N) ? Bp[3] : 0.0f;
        }
        As[0][ak + 0][am] = av.x;
        As[0][ak + 1][am] = av.y;
        As[0][ak + 2][am] = av.z;
        As[0][ak + 3][am] = av.w;
        *(float4*)&Bs[0][bk][bj] = bv;
    }
    __syncthreads();

    int buf = 0;
    for (int t = 0; t < ntiles; t++) {
        float4 avn, bvn;
        const bool more = (t + 1 < ntiles);
        if (more) {
            avn = *(const float4*)(Arow + (t + 1) * TK);
            int kk = k0 + (t + 1) * TK + bk;
            const float* Bp = B + (size_t)kk * N + nBase + bj;
            if (nfull) bvn = *(const float4*)Bp;
            else {
                bvn.x = (nBase + bj + 0 < N) ? Bp[0] : 0.0f;
                bvn.y = (nBase + bj + 1 < N) ? Bp[1] : 0.0f;
                bvn.z = (nBase + bj + 2 < N) ? Bp[2] : 0.0f;
                bvn.w = (nBase + bj + 3 < N) ? Bp[3] : 0.0f;
            }
        }

#pragma unroll
        for (int kx = 0; kx < TK; kx++) {
            ulonglong2 ap = *(const ulonglong2*)&As[buf][kx][ty * 4];
            float4 bq = *(const float4*)&Bs[buf][kx][tx * 4];
            unsigned long long b0 = dup_f(bq.x);
            unsigned long long b1 = dup_f(bq.y);
            unsigned long long b2 = dup_f(bq.z);
            unsigned long long b3 = dup_f(bq.w);
            fma2(acc[0][0], ap.x, b0);
            fma2(acc[0][1], ap.x, b1);
            fma2(acc[0][2], ap.x, b2);
            fma2(acc[0][3], ap.x, b3);
            fma2(acc[1][0], ap.y, b0);
            fma2(acc[1][1], ap.y, b1);
            fma2(acc[1][2], ap.y, b2);
            fma2(acc[1][3], ap.y, b3);
        }

        if (more) {
            int nb = buf ^ 1;
            As[nb][ak + 0][am] = avn.x;
            As[nb][ak + 1][am] = avn.y;
            As[nb][ak + 2][am] = avn.z;
            As[nb][ak + 3][am] = avn.w;
            *(float4*)&Bs[nb][bk][bj] = bvn;
            __syncthreads();
            buf = nb;
        }
    }

#pragma unroll
    for (int p = 0; p < 2; p++) {
        int m = mBase + ty * 4 + p * 2;
#pragma unroll
        for (int q = 0; q < 4; q++) {
            float2 v = unpack2(acc[p][q]);
            int col = nBase + tx * 4 + q;
            if (col < N) {
                P[(size_t)m * N + col] = v.x;
                P[(size_t)(m + 1) * N + col] = v.y;
            }
        }
    }
}

// fused cls+loc head GEMM: grid.x in [0,8): 0-1 -> Wc (N=81), 2-7 -> Wl (N=324)
__global__ __launch_bounds__(256) void gemm_heads(
    const float* __restrict__ Wc, const float* __restrict__ Wl) {
    int bx = blockIdx.x;
    const float* Bsel;
    int N, nBase;
    float* P;
    if (bx < 2) {
        Bsel = Wc; N = 81; nBase = bx * BN;
        P = g_part + (size_t)blockIdx.z * NROIS * 81;
    } else {
        Bsel = Wl; N = 324; nBase = (bx - 2) * BN;
        P = g_part + LOC_OFF + (size_t)blockIdx.z * NROIS * 324;
    }
    gemm_core64(g_h2, Bsel, N, 1024, 256, blockIdx.z,
                blockIdx.y * BM, nBase, P);
}

// fixed-order split reduction + bias + relu (FC1/FC2 outputs)
__global__ void reduce_bias(const float* __restrict__ bias, int outSel,
                            int splits) {
    float* out = outSel ? g_h2 : g_h1;
    int idx = blockIdx.x * 256 + threadIdx.x;   // grid covers 256*1024
    const int MN = NROIS * 1024;
    float s = 0.0f;
    for (int sp = 0; sp < splits; sp++) s += g_part[(size_t)sp * MN + idx];
    s += bias[idx & 1023];
    out[idx] = fmaxf(s, 0.0f);
}

// ---------------------------------------------------------------------------
// Fused head epilogue: reduce cls/loc partials + bias, softmax, box decode,
// accumulate, argmax, roi update, valid mask. One block per roi, 128 threads.
// ---------------------------------------------------------------------------
__global__ void head_post(const float* __restrict__ bc,
                          const float* __restrict__ bl, int stage) {
    const int n = blockIdx.x;
    const int tid = threadIdx.x;

    __shared__ float sl[81];
    __shared__ float sloc[324];
    __shared__ float ssc[80];
    __shared__ float sbox[80][4];
    __shared__ float sred[128];
    __shared__ int sidx[128];

    if (tid < 81) {
        float s = 0.0f;
#pragma unroll
        for (int sp = 0; sp < 4; sp++)
            s += g_part[(size_t)sp * (NROIS * 81) + n * 81 + tid];
        sl[tid] = s + bc[tid];
    }
    for (int i = tid; i < 324; i += 128) {
        float s = 0.0f;
#pragma unroll
        for (int sp = 0; sp < 4; sp++)
            s += g_part[LOC_OFF + (size_t)sp * (NROIS * 324) + n * 324 + i];
        sloc[i] = s + bl[i];
    }
    __syncthreads();

    // softmax max
    float m = (tid < 81) ? sl[tid] : -1e30f;
    sred[tid] = m;
    __syncthreads();
    for (int off = 64; off > 0; off >>= 1) {
        if (tid < off) sred[tid] = fmaxf(sred[tid], sred[tid + off]);
        __syncthreads();
    }
    const float M = sred[0];
    __syncthreads();

    // exp-sum
    float e = (tid < 81) ? expf(sl[tid] - M) : 0.0f;
    sred[tid] = e;
    __syncthreads();
    for (int off = 64; off > 0; off >>= 1) {
        if (tid < off) sred[tid] += sred[tid + off];
        __syncthreads();
    }
    const float S = sred[0];
    __syncthreads();
    if (tid >= 1 && tid < 81) ssc[tid - 1] = e / S;
    __syncthreads();

    const float r0 = g_roi[n * 4 + 0];
    const float r1 = g_roi[n * 4 + 1];
    const float r2 = g_roi[n * 4 + 2];
    const float r3 = g_roi[n * 4 + 3];
    const float chy = r2 - r0, chx = r3 - r1;
    const float cy = r0 + chy * 0.5f, cx = r1 + chx * 0.5f;
    const float4 stds = c_stds[stage];

    if (tid < 80) {
        const int j = tid;
        g_pres[n * 80 + j] += ssc[j];
        const float* lp = sloc + (j + 1) * 4;
        float l0 = lp[0] * stds.x;
        float l1 = lp[1] * stds.y;
        float l2 = lp[2] * stds.z;
        float l3 = lp[3] * stds.w;
        float ty_ = l0 * chy + cy;
        float tx_ = l1 * chx + cx;
        float hy = expf(l2) * chy;
        float hx = expf(l3) * chx;
        float b0 = ty_ - hy * 0.5f;
        float b1 = tx_ - hx * 0.5f;
        float b2 = ty_ + hy * 0.5f;
        float b3 = tx_ + hx * 0.5f;
        sbox[j][0] = b0; sbox[j][1] = b1; sbox[j][2] = b2; sbox[j][3] = b3;
        float* pb = g_preb + (size_t)(n * 80 + j) * 4;
        pb[0] += b0; pb[1] += b1; pb[2] += b2; pb[3] += b3;
    }

    // argmax (first occurrence on ties)
    sred[tid] = (tid < 80) ? ssc[tid] : -1e30f;
    sidx[tid] = (tid < 80) ? tid : (1 << 30);
    __syncthreads();
    for (int off = 64; off > 0; off >>= 1) {
        if (tid < off) {
            float v2 = sred[tid + off];
            int i2 = sidx[tid + off];
            if (v2 > sred[tid] || (v2 == sred[tid] && i2 < sidx[tid])) {
                sred[tid] = v2;
                sidx[tid] = i2;
            }
        }
        __syncthreads();
    }
    if (tid == 0) {
        int best = sidx[0];
        float nr0 = fminf(fmaxf(sbox[best][0], 0.0f), 1024.0f);
        float nr1 = fminf(fmaxf(sbox[best][1], 0.0f), 1024.0f);
        float nr2 = fminf(fmaxf(sbox[best][2], 0.0f), 1024.0f);
        float nr3 = fminf(fmaxf(sbox[best][3], 0.0f), 1024.0f);
        g_roi[n * 4 + 0] = nr0;
        g_roi[n * 4 + 1] = nr1;
        g_roi[n * 4 + 2] = nr2;
        g_roi[n * 4 + 3] = nr3;
        if (stage < 2) {
            float hy = nr2 - nr0, hx = nr3 - nr1;
            if (!(hy >= 16.0f && hx >= 16.0f)) g_valid[n] = 0.0f;
        }
    }
}

// final: d_out = [pre_b/3*m (81920) | pre_s/3*m (20480)]
__global__ void finalize_kernel(float* __restrict__ out) {
    int idx = blockIdx.x * 256 + threadIdx.x;   // grid covers 81920
    if (idx < NROIS * NUM_CLS * 4) {
        int n = idx / (NUM_CLS * 4);
        out[idx] = g_preb[idx] * (1.0f / 3.0f) * g_valid[n];
    }
    if (idx < NROIS * NUM_CLS) {
        int n = idx / NUM_CLS;
        out[NROIS * NUM_CLS * 4 + idx] = g_pres[idx] * (1.0f / 3.0f) * g_valid[n];
    }
}

// ---------------------------------------------------------------------------
// launch
// ---------------------------------------------------------------------------
extern "C" void kernel_launch(void* const* d_in, const int* in_sizes, int n_in,
                              void* d_out, int out_size) {
    (void)in_sizes; (void)n_in; (void)out_size;
    const float* P0 = (const float*)d_in[0];
    const float* P1 = (const float*)d_in[1];
    const float* P2 = (const float*)d_in[2];
    const float* P3 = (const float*)d_in[3];
    const float* rois = (const float*)d_in[4];

    transpose_all<<<dim3(2720, 8), dim3(32, 8)>>>(P0, P1, P2, P3);
    init_state<<<320, 256>>>(rois);

    for (int s = 0; s < 3; s++) {
        const float* W1 = (const float*)d_in[5 + 8 * s + 0];
        const float* b1 = (const float*)d_in[5 + 8 * s + 1];
        const float* W2 = (const float*)d_in[5 + 8 * s + 2];
        const float* b2 = (const float*)d_in[5 + 8 * s + 3];
        const float* Wc = (const float*)d_in[5 + 8 * s + 4];
        const float* bc = (const float*)d_in[5 + 8 * s + 5];
        const float* Wl = (const float*)d_in[5 + 8 * s + 6];
        const float* bl = (const float*)d_in[5 + 8 * s + 7];

        roialign_kernel<<<NROIS, 256>>>();

        // FC1: [256,12544] x [12544,1024], 128x128 tiles, split-K=8
        gemm128<true><<<dim3(8, 2, 8), 256>>>(W1, 0, 1024, 12544, 1568);
        reduce_bias<<<1024, 256>>>(b1, 0, 8);

        // FC2: [256,1024] x [1024,1024], 128x128 tiles, split-K=8
        gemm128<false><<<dim3(8, 2, 8), 256>>>(W2, 1, 1024, 1024, 128);
        reduce_bias<<<1024, 256>>>(b2, 1, 8);

        // heads (cls + loc fused), split-K=4
        gemm_heads<<<dim3(8, 4, 4), 256>>>(Wc, Wl);
        head_post<<<NROIS, 128>>>(bc, bl, s);
    }

    finalize_kernel<<<320, 256>>>((float*)d_out);
}

// round 10
// speedup vs baseline: 1.1259x; 1.0025x over previous
#include <cuda_runtime.h>
#include <cuda_bf16.h>
#include <math.h>

// ---------------------------------------------------------------------------
// Problem constants
// ---------------------------------------------------------------------------
#define NUM_CLS 80
#define NROIS   256
#define KFEAT   12544   // 256 * 49
#define H1DIM   1024
#define LOC_OFF 82944   // 4*256*81 floats into g_part (loc partials start)

// scratch (device globals; no allocation)
__device__ float g_T0[65536 * 256];   // P0 transposed HWC
__device__ float g_T1[16384 * 256];
__device__ float g_T2[4096 * 256];
__device__ float g_T3[1024 * 256];
__device__ float g_pool[NROIS * KFEAT];        // [n][bin*256 + c]
__device__ float g_part[8 * NROIS * 1024];     // split-K partials (reused)
__device__ float g_h1[NROIS * H1DIM];
__device__ float g_h2[NROIS * H1DIM];
__device__ float g_roi[NROIS * 4];
__device__ float g_valid[NROIS];
__device__ float g_preb[NROIS * NUM_CLS * 4];
__device__ float g_pres[NROIS * NUM_CLS];

__constant__ float4 c_stds[3] = {
    {0.1f, 0.1f, 0.2f, 0.2f},
    {0.05f, 0.05f, 0.1f, 0.1f},
    {1.0f / 30.0f, 1.0f / 30.0f, 1.0f / 15.0f, 1.0f / 15.0f}
};

// ---------------------------------------------------------------------------
// f32x2 packed FMA helpers (sm_103a)
// ---------------------------------------------------------------------------
__device__ __forceinline__ unsigned long long dup_f(float x) {
    unsigned long long r;
    asm("mov.b64 %0, {%1, %1};" : "=l"(r) : "f"(x));
    return r;
}
__device__ __forceinline__ void fma2(unsigned long long& d, unsigned long long a,
                                     unsigned long long b) {
    asm("fma.rn.f32x2 %0, %1, %2, %0;" : "+l"(d) : "l"(a), "l"(b));
}
__device__ __forceinline__ float2 unpack2(unsigned long long v) {
    float2 r;
    asm("mov.b64 {%0, %1}, %2;" : "=f"(r.x), "=f"(r.y) : "l"(v));
    return r;
}

// ---------------------------------------------------------------------------
// Fused transpose: all 4 levels [C][HW] -> [HW][C]
// grid = (2720, 8), block = (32, 8)
// ---------------------------------------------------------------------------
__global__ void transpose_all(const float* __restrict__ P0,
                              const float* __restrict__ P1,
                              const float* __restrict__ P2,
                              const float* __restrict__ P3) {
    __shared__ float tile[32][33];
    int bx = blockIdx.x;
    int p, HW;
    const float* src;
    float* dst;
    if (bx < 2048)      { p = bx;        HW = 65536; src = P0; dst = g_T0; }
    else if (bx < 2560) { p = bx - 2048; HW = 16384; src = P1; dst = g_T1; }
    else if (bx < 2688) { p = bx - 2560; HW = 4096;  src = P2; dst = g_T2; }
    else                { p = bx - 2688; HW = 1024;  src = P3; dst = g_T3; }

    int pBase = p * 32;
    int cBase = blockIdx.y * 32;
    int tx = threadIdx.x, ty = threadIdx.y;
#pragma unroll
    for (int r = 0; r < 4; r++)
        tile[ty + 8 * r][tx] = src[(size_t)(cBase + ty + 8 * r) * HW + pBase + tx];
    __syncthreads();
#pragma unroll
    for (int r = 0; r < 4; r++)
        dst[(size_t)(pBase + ty + 8 * r) * 256 + cBase + tx] = tile[tx][ty + 8 * r];
}

// ---------------------------------------------------------------------------
// Init accumulators / roi state
// ---------------------------------------------------------------------------
__global__ void init_state(const float* __restrict__ rois) {
    int idx = blockIdx.x * 256 + threadIdx.x;   // grid covers 81920
    if (idx < NROIS * NUM_CLS * 4) g_preb[idx] = 0.0f;
    if (idx < NROIS * NUM_CLS)     g_pres[idx] = 0.0f;
    if (idx < NROIS * 4)           g_roi[idx] = rois[idx];
    if (idx < NROIS)               g_valid[idx] = 1.0f;
}

// ---------------------------------------------------------------------------
// ROIAlign (out=7, SR=2) on channels-last features.
// ---------------------------------------------------------------------------
__global__ void roialign_kernel() {
    const int n = blockIdx.x;
    const int tid = threadIdx.x;

    __shared__ int   s_iy0[14], s_iy1[14], s_ix0[14], s_ix1[14];
    __shared__ float s_ly[14], s_lx[14];
    __shared__ int   s_vy[14], s_vx[14];
    __shared__ int   s_lvl;

    const float r0 = g_roi[n * 4 + 0];
    const float r1 = g_roi[n * 4 + 1];
    const float r2 = g_roi[n * 4 + 2];
    const float r3 = g_roi[n * 4 + 3];

    if (tid == 0) {
        float area = (r2 - r0 + 1.0f) * (r3 - r1 + 1.0f);
        float lv = floorf(4.0f + log2f(sqrtf(area) / 224.0f));
        lv = fminf(fmaxf(lv, 2.0f), 5.0f) - 2.0f;
        s_lvl = (int)lv;
    }
    __syncthreads();

    const int l = s_lvl;
    const int Hdims[4] = {256, 128, 64, 32};
    const float scales[4] = {0.25f, 0.125f, 0.0625f, 0.03125f};
    const int H = Hdims[l];
    const int W = H;
    const float scale = scales[l];

    if (tid < 28) {
        bool isx = tid >= 14;
        int t = isx ? tid - 14 : tid;
        float a  = isx ? r1 : r0;
        float b2 = isx ? r3 : r2;
        float lo = a * scale;
        float len = fmaxf(b2 * scale - lo, 1.0f);
        float g = (float)(t >> 1) + ((float)(t & 1) + 0.5f) * 0.5f;
        float coord = lo + g * (len / 7.0f);
        int v = (coord > -1.0f) && (coord < (float)H);
        float cc = fminf(fmaxf(coord, 0.0f), (float)H - 1.0f);
        float f0 = floorf(cc);
        int i0 = (int)f0;
        int i1 = min(i0 + 1, H - 1);
        float fr = cc - f0;
        if (isx) { s_vx[t] = v; s_ix0[t] = i0; s_ix1[t] = i1; s_lx[t] = fr; }
        else     { s_vy[t] = v; s_iy0[t] = i0; s_iy1[t] = i1; s_ly[t] = fr; }
    }
    __syncthreads();

    const float* Ts[4] = {g_T0, g_T1, g_T2, g_T3};
    const float4* F = (const float4*)Ts[l];

    const int c4 = tid & 63;    // channel group (4 channels)
    const int grp = tid >> 6;   // 4 bin groups
    float4* outp = (float4*)(g_pool + (size_t)n * KFEAT);

    for (int bin = grp; bin < 49; bin += 4) {
        int oy = bin / 7;
        int ox = bin - oy * 7;
        float4 acc = {0.f, 0.f, 0.f, 0.f};
#pragma unroll
        for (int jy = 0; jy < 2; jy++) {
            int sy = oy * 2 + jy;
            int vy = s_vy[sy];
            float ly = s_ly[sy];
            int y0 = s_iy0[sy], y1i = s_iy1[sy];
#pragma unroll
            for (int jx = 0; jx < 2; jx++) {
                int sx = ox * 2 + jx;
                if (vy && s_vx[sx]) {
                    float lx = s_lx[sx];
                    int x0 = s_ix0[sx], x1i = s_ix1[sx];
                    float4 f00 = F[(size_t)(y0 * W + x0) * 64 + c4];
                    float4 f01 = F[(size_t)(y0 * W + x1i) * 64 + c4];
                    float4 f10 = F[(size_t)(y1i * W + x0) * 64 + c4];
                    float4 f11 = F[(size_t)(y1i * W + x1i) * 64 + c4];
                    float w00 = (1.f - ly) * (1.f - lx);
                    float w01 = (1.f - ly) * lx;
                    float w10 = ly * (1.f - lx);
                    float w11 = ly * lx;
                    acc.x += f00.x * w00 + f01.x * w01 + f10.x * w10 + f11.x * w11;
                    acc.y += f00.y * w00 + f01.y * w01 + f10.y * w10 + f11.y * w11;
                    acc.z += f00.z * w00 + f01.z * w01 + f10.z * w10 + f11.z * w11;
                    acc.w += f00.w * w00 + f01.w * w01 + f10.w * w10 + f11.w * w11;
                }
            }
        }
        acc.x *= 0.25f; acc.y *= 0.25f; acc.z *= 0.25f; acc.w *= 0.25f;
        outp[bin * 64 + c4] = acc;
    }
}

// ---------------------------------------------------------------------------
// 128x128 split-K GEMM, 512 threads, 4x8 outputs/thread, n-packed f32x2 acc.
// C[M=256, N(mult of 128)] = A[256, Ktot] * B[Ktot, N] -> per-split partials.
// PERM: B row remap k -> (k%256)*49 + (k/256) (pool layout -> W1 rows).
// grid = (N/128, M/128, splits). Kc must be a multiple of 16.
// ---------------------------------------------------------------------------
template <bool PERM>
__global__ __launch_bounds__(512) void gemm512(
    const float* __restrict__ B, int Asel, int N, int Ktot, int Kc) {
    const float* A = (Asel == 0) ? g_pool : ((Asel == 1) ? g_h1 : g_h2);

    __shared__ float As[2][16][132];
    __shared__ float Bs[2][16][132];

    const int tid = threadIdx.x;
    const int k0 = blockIdx.z * Kc;
    const int mBase = blockIdx.y * 128;
    const int nBase = blockIdx.x * 128;

    // A-load: thread -> row lm (0..127), k-slice lk..lk+3
    const int lm = tid >> 2;
    const int lk = (tid & 3) * 4;
    // B-load: row bk (0..15), cols bj..bj+3
    const int bk = tid >> 5;
    const int bj = (tid & 31) * 4;

    // compute mapping: 16 warps as 4(M) x 4(N); lane as 8(m-groups of 4) x 4(n-groups of 8)
    const int wid = tid >> 5, lane = tid & 31;
    const int tm = (wid >> 2) * 32 + (lane >> 2) * 4;   // rows tm..tm+3
    const int tn = (wid & 3) * 32 + (lane & 3) * 8;     // cols tn..tn+7

    unsigned long long acc[4][4];   // [m][n-pair]
#pragma unroll
    for (int p = 0; p < 4; p++)
#pragma unroll
        for (int q = 0; q < 4; q++) acc[p][q] = 0ull;

    const float* Arow = A + (size_t)(mBase + lm) * Ktot + k0 + lk;
    const int ntiles = Kc / 16;

    // ---- prologue: tile 0 -> smem[0]
    {
        float4 av = *(const float4*)(Arow);
        int kk = k0 + bk;
        int krow = PERM ? ((kk & 255) * 49 + (kk >> 8)) : kk;
        float4 bv = *(const float4*)(B + (size_t)krow * N + nBase + bj);
        As[0][lk + 0][lm] = av.x;  As[0][lk + 1][lm] = av.y;
        As[0][lk + 2][lm] = av.z;  As[0][lk + 3][lm] = av.w;
        *(float4*)&Bs[0][bk][bj] = bv;
    }
    __syncthreads();

    int buf = 0;
    for (int t = 0; t < ntiles; t++) {
        float4 avn, bvn;
        const bool more = (t + 1 < ntiles);
        if (more) {
            avn = *(const float4*)(Arow + (t + 1) * 16);
            int kk = k0 + (t + 1) * 16 + bk;
            int krow = PERM ? ((kk & 255) * 49 + (kk >> 8)) : kk;
            bvn = *(const float4*)(B + (size_t)krow * N + nBase + bj);
        }

#pragma unroll
        for (int kx = 0; kx < 16; kx++) {
            float4 af = *(const float4*)&As[buf][kx][tm];
            ulonglong2 b0 = *(const ulonglong2*)&Bs[buf][kx][tn];
            ulonglong2 b1 = *(const ulonglong2*)&Bs[buf][kx][tn + 4];
            unsigned long long a0 = dup_f(af.x);
            unsigned long long a1 = dup_f(af.y);
            unsigned long long a2 = dup_f(af.z);
            unsigned long long a3 = dup_f(af.w);
            fma2(acc[0][0], a0, b0.x); fma2(acc[0][1], a0, b0.y);
            fma2(acc[0][2], a0, b1.x); fma2(acc[0][3], a0, b1.y);
            fma2(acc[1][0], a1, b0.x); fma2(acc[1][1], a1, b0.y);
            fma2(acc[1][2], a1, b1.x); fma2(acc[1][3], a1, b1.y);
            fma2(acc[2][0], a2, b0.x); fma2(acc[2][1], a2, b0.y);
            fma2(acc[2][2], a2, b1.x); fma2(acc[2][3], a2, b1.y);
            fma2(acc[3][0], a3, b0.x); fma2(acc[3][1], a3, b0.y);
            fma2(acc[3][2], a3, b1.x); fma2(acc[3][3], a3, b1.y);
        }

        if (more) {
            int nb = buf ^ 1;
            As[nb][lk + 0][lm] = avn.x;  As[nb][lk + 1][lm] = avn.y;
            As[nb][lk + 2][lm] = avn.z;  As[nb][lk + 3][lm] = avn.w;
            *(float4*)&Bs[nb][bk][bj] = bvn;
            __syncthreads();
            buf = nb;
        }
    }

    // epilogue: packed pairs are adjacent columns -> direct 16B stores
    float* P = g_part + (size_t)blockIdx.z * NROIS * N;
#pragma unroll
    for (int p = 0; p < 4; p++) {
        float* rp = P + (size_t)(mBase + tm + p) * N + nBase + tn;
        ulonglong2 v0; v0.x = acc[p][0]; v0.y = acc[p][1];
        ulonglong2 v1; v1.x = acc[p][2]; v1.y = acc[p][3];
        *(ulonglong2*)(rp) = v0;
        *(ulonglong2*)(rp + 4) = v1;
    }
}

// ---------------------------------------------------------------------------
// 64x64 split-K GEMM core (kept for the small cls/loc head GEMMs)
// ---------------------------------------------------------------------------
#define BM 64
#define BN 64
#define TK 16

__device__ __forceinline__ void gemm_core64(
    const float* __restrict__ A, const float* __restrict__ B,
    int N, int Ktot, int Kc, int split, int mBase, int nBase,
    float* __restrict__ P) {

    __shared__ float As[2][TK][BM + 4];
    __shared__ float Bs[2][TK][BN + 4];

    const int tid = threadIdx.x;
    const int k0 = split * Kc;

    const int am = tid >> 2;
    const int ak = (tid & 3) * 4;
    const int bk = tid >> 4;
    const int bj = (tid & 15) * 4;
    const int tx = tid & 15;
    const int ty = tid >> 4;

    unsigned long long acc[2][4];
#pragma unroll
    for (int p = 0; p < 2; p++)
#pragma unroll
        for (int q = 0; q < 4; q++) acc[p][q] = 0ull;

    const bool nfull = ((nBase + BN) <= N) && ((N & 3) == 0);
    const float* Arow = A + (size_t)(mBase + am) * Ktot + k0 + ak;
    const int ntiles = Kc / TK;

    {
        float4 av = *(const float4*)(Arow);
        int kk = k0 + bk;
        const float* Bp = B + (size_t)kk * N + nBase + bj;
        float4 bv;
        if (nfull) bv = *(const float4*)Bp;
        else {
            bv.x = (nBase + bj + 0 < N) ? Bp[0] : 0.0f;
            bv.y = (nBase + bj + 1 < N) ? Bp[1] : 0.0f;
            bv.z = (nBase + bj + 2 < N) ? Bp[2] : 0.0f;
            bv.w = (nBase + bj + 3 < N) ? Bp[3] : 0.0f;
        }
        As[0][ak + 0][am] = av.x;
        As[0][ak + 1][am] = av.y;
        As[0][ak + 2][am] = av.z;
        As[0][ak + 3][am] = av.w;
        *(float4*)&Bs[0][bk][bj] = bv;
    }
    __syncthreads();

    int buf = 0;
    for (int t = 0; t < ntiles; t++) {
        float4 avn, bvn;
        const bool more = (t + 1 < ntiles);
        if (more) {
            avn = *(const float4*)(Arow + (t + 1) * TK);
            int kk = k0 + (t + 1) * TK + bk;
            const float* Bp = B + (size_t)kk * N + nBase + bj;
            if (nfull) bvn = *(const float4*)Bp;
            else {
                bvn.x = (nBase + bj + 0 < N) ? Bp[0] : 0.0f;
                bvn.y = (nBase + bj + 1 < N) ? Bp[1] : 0.0f;
                bvn.z = (nBase + bj + 2 < N) ? Bp[2] : 0.0f;
                bvn.w = (nBase + bj + 3 < N) ? Bp[3] : 0.0f;
            }
        }

#pragma unroll
        for (int kx = 0; kx < TK; kx++) {
            ulonglong2 ap = *(const ulonglong2*)&As[buf][kx][ty * 4];
            float4 bq = *(const float4*)&Bs[buf][kx][tx * 4];
            unsigned long long b0 = dup_f(bq.x);
            unsigned long long b1 = dup_f(bq.y);
            unsigned long long b2 = dup_f(bq.z);
            unsigned long long b3 = dup_f(bq.w);
            fma2(acc[0][0], ap.x, b0);
            fma2(acc[0][1], ap.x, b1);
            fma2(acc[0][2], ap.x, b2);
            fma2(acc[0][3], ap.x, b3);
            fma2(acc[1][0], ap.y, b0);
            fma2(acc[1][1], ap.y, b1);
            fma2(acc[1][2], ap.y, b2);
            fma2(acc[1][3], ap.y, b3);
        }

        if (more) {
            int nb = buf ^ 1;
            As[nb][ak + 0][am] = avn.x;
            As[nb][ak + 1][am] = avn.y;
            As[nb][ak + 2][am] = avn.z;
            As[nb][ak + 3][am] = avn.w;
            *(float4*)&Bs[nb][bk][bj] = bvn;
            __syncthreads();
            buf = nb;
        }
    }

#pragma unroll
    for (int p = 0; p < 2; p++) {
        int m = mBase + ty * 4 + p * 2;
#pragma unroll
        for (int q = 0; q < 4; q++) {
            float2 v = unpack2(acc[p][q]);
            int col = nBase + tx * 4 + q;
            if (col < N) {
                P[(size_t)m * N + col] = v.x;
                P[(size_t)(m + 1) * N + col] = v.y;
            }
        }
    }
}

// fused cls+loc head GEMM: grid.x in [0,8): 0-1 -> Wc (N=81), 2-7 -> Wl (N=324)
__global__ __launch_bounds__(256) void gemm_heads(
    const float* __restrict__ Wc, const float* __restrict__ Wl) {
    int bx = blockIdx.x;
    const float* Bsel;
    int N, nBase;
    float* P;
    if (bx < 2) {
        Bsel = Wc; N = 81; nBase = bx * BN;
        P = g_part + (size_t)blockIdx.z * NROIS * 81;
    } else {
        Bsel = Wl; N = 324; nBase = (bx - 2) * BN;
        P = g_part + LOC_OFF + (size_t)blockIdx.z * NROIS * 324;
    }
    gemm_core64(g_h2, Bsel, N, 1024, 256, blockIdx.z,
                blockIdx.y * BM, nBase, P);
}

// fixed-order split reduction + bias + relu (FC1/FC2 outputs)
__global__ void reduce_bias(const float* __restrict__ bias, int outSel,
                            int splits) {
    float* out = outSel ? g_h2 : g_h1;
    int idx = blockIdx.x * 256 + threadIdx.x;   // grid covers 256*1024
    const int MN = NROIS * 1024;
    float s = 0.0f;
    for (int sp = 0; sp < splits; sp++) s += g_part[(size_t)sp * MN + idx];
    s += bias[idx & 1023];
    out[idx] = fmaxf(s, 0.0f);
}

// ---------------------------------------------------------------------------
// Fused head epilogue: reduce cls/loc partials + bias, softmax, box decode,
// accumulate, argmax, roi update, valid mask. One block per roi, 128 threads.
// ---------------------------------------------------------------------------
__global__ void head_post(const float* __restrict__ bc,
                          const float* __restrict__ bl, int stage) {
    const int n = blockIdx.x;
    const int tid = threadIdx.x;

    __shared__ float sl[81];
    __shared__ float sloc[324];
    __shared__ float ssc[80];
    __shared__ float sbox[80][4];
    __shared__ float sred[128];
    __shared__ int sidx[128];

    if (tid < 81) {
        float s = 0.0f;
#pragma unroll
        for (int sp = 0; sp < 4; sp++)
            s += g_part[(size_t)sp * (NROIS * 81) + n * 81 + tid];
        sl[tid] = s + bc[tid];
    }
    for (int i = tid; i < 324; i += 128) {
        float s = 0.0f;
#pragma unroll
        for (int sp = 0; sp < 4; sp++)
            s += g_part[LOC_OFF + (size_t)sp * (NROIS * 324) + n * 324 + i];
        sloc[i] = s + bl[i];
    }
    __syncthreads();

    // softmax max
    float m = (tid < 81) ? sl[tid] : -1e30f;
    sred[tid] = m;
    __syncthreads();
    for (int off = 64; off > 0; off >>= 1) {
        if (tid < off) sred[tid] = fmaxf(sred[tid], sred[tid + off]);
        __syncthreads();
    }
    const float M = sred[0];
    __syncthreads();

    // exp-sum
    float e = (tid < 81) ? expf(sl[tid] - M) : 0.0f;
    sred[tid] = e;
    __syncthreads();
    for (int off = 64; off > 0; off >>= 1) {
        if (tid < off) sred[tid] += sred[tid + off];
        __syncthreads();
    }
    const float S = sred[0];
    __syncthreads();
    if (tid >= 1 && tid < 81) ssc[tid - 1] = e / S;
    __syncthreads();

    const float r0 = g_roi[n * 4 + 0];
    const float r1 = g_roi[n * 4 + 1];
    const float r2 = g_roi[n * 4 + 2];
    const float r3 = g_roi[n * 4 + 3];
    const float chy = r2 - r0, chx = r3 - r1;
    const float cy = r0 + chy * 0.5f, cx = r1 + chx * 0.5f;
    const float4 stds = c_stds[stage];

    if (tid < 80) {
        const int j = tid;
        g_pres[n * 80 + j] += ssc[j];
        const float* lp = sloc + (j + 1) * 4;
        float l0 = lp[0] * stds.x;
        float l1 = lp[1] * stds.y;
        float l2 = lp[2] * stds.z;
        float l3 = lp[3] * stds.w;
        float ty_ = l0 * chy + cy;
        float tx_ = l1 * chx + cx;
        float hy = expf(l2) * chy;
        float hx = expf(l3) * chx;
        float b0 = ty_ - hy * 0.5f;
        float b1 = tx_ - hx * 0.5f;
        float b2 = ty_ + hy * 0.5f;
        float b3 = tx_ + hx * 0.5f;
        sbox[j][0] = b0; sbox[j][1] = b1; sbox[j][2] = b2; sbox[j][3] = b3;
        float* pb = g_preb + (size_t)(n * 80 + j) * 4;
        pb[0] += b0; pb[1] += b1; pb[2] += b2; pb[3] += b3;
    }

    // argmax (first occurrence on ties)
    sred[tid] = (tid < 80) ? ssc[tid] : -1e30f;
    sidx[tid] = (tid < 80) ? tid : (1 << 30);
    __syncthreads();
    for (int off = 64; off > 0; off >>= 1) {
        if (tid < off) {
            float v2 = sred[tid + off];
            int i2 = sidx[tid + off];
            if (v2 > sred[tid] || (v2 == sred[tid] && i2 < sidx[tid])) {
                sred[tid] = v2;
                sidx[tid] = i2;
            }
        }
        __syncthreads();
    }
    if (tid == 0) {
        int best = sidx[0];
        float nr0 = fminf(fmaxf(sbox[best][0], 0.0f), 1024.0f);
        float nr1 = fminf(fmaxf(sbox[best][1], 0.0f), 1024.0f);
        float nr2 = fminf(fmaxf(sbox[best][2], 0.0f), 1024.0f);
        float nr3 = fminf(fmaxf(sbox[best][3], 0.0f), 1024.0f);
        g_roi[n * 4 + 0] = nr0;
        g_roi[n * 4 + 1] = nr1;
        g_roi[n * 4 + 2] = nr2;
        g_roi[n * 4 + 3] = nr3;
        if (stage < 2) {
            float hy = nr2 - nr0, hx = nr3 - nr1;
            if (!(hy >= 16.0f && hx >= 16.0f)) g_valid[n] = 0.0f;
        }
    }
}

// final: d_out = [pre_b/3*m (81920) | pre_s/3*m (20480)]
__global__ void finalize_kernel(float* __restrict__ out) {
    int idx = blockIdx.x * 256 + threadIdx.x;   // grid covers 81920
    if (idx < NROIS * NUM_CLS * 4) {
        int n = idx / (NUM_CLS * 4);
        out[idx] = g_preb[idx] * (1.0f / 3.0f) * g_valid[n];
    }
    if (idx < NROIS * NUM_CLS) {
        int n = idx / NUM_CLS;
        out[NROIS * NUM_CLS * 4 + idx] = g_pres[idx] * (1.0f / 3.0f) * g_valid[n];
    }
}

// ---------------------------------------------------------------------------
// launch
// ---------------------------------------------------------------------------
extern "C" void kernel_launch(void* const* d_in, const int* in_sizes, int n_in,
                              void* d_out, int out_size) {
    (void)in_sizes; (void)n_in; (void)out_size;
    const float* P0 = (const float*)d_in[0];
    const float* P1 = (const float*)d_in[1];
    const float* P2 = (const float*)d_in[2];
    const float* P3 = (const float*)d_in[3];
    const float* rois = (const float*)d_in[4];

    transpose_all<<<dim3(2720, 8), dim3(32, 8)>>>(P0, P1, P2, P3);
    init_state<<<320, 256>>>(rois);

    for (int s = 0; s < 3; s++) {
        const float* W1 = (const float*)d_in[5 + 8 * s + 0];
        const float* b1 = (const float*)d_in[5 + 8 * s + 1];
        const float* W2 = (const float*)d_in[5 + 8 * s + 2];
        const float* b2 = (const float*)d_in[5 + 8 * s + 3];
        const float* Wc = (const float*)d_in[5 + 8 * s + 4];
        const float* bc = (const float*)d_in[5 + 8 * s + 5];
        const float* Wl = (const float*)d_in[5 + 8 * s + 6];
        const float* bl = (const float*)d_in[5 + 8 * s + 7];

        roialign_kernel<<<NROIS, 256>>>();

        // FC1: [256,12544] x [12544,1024], 128x128 tiles, split-K=8
        gemm512<true><<<dim3(8, 2, 8), 512>>>(W1, 0, 1024, 12544, 1568);
        reduce_bias<<<1024, 256>>>(b1, 0, 8);

        // FC2: [256,1024] x [1024,1024], 128x128 tiles, split-K=8
        gemm512<false><<<dim3(8, 2, 8), 512>>>(W2, 1, 1024, 1024, 128);
        reduce_bias<<<1024, 256>>>(b2, 1, 8);

        // heads (cls + loc fused), split-K=4
        gemm_heads<<<dim3(8, 4, 4), 256>>>(Wc, Wl);
        head_post<<<NROIS, 128>>>(bc, bl, s);
    }

    finalize_kernel<<<320, 256>>>((float*)d_out);
}